// round 8
// baseline (speedup 1.0000x reference)
#include <cuda_runtime.h>
#include <cstdint>

#define NN 8192
#define CC 256
#define TOPK 17
#define KNN 16

// ---------------- scratch (device globals: allocation-free) ----------------
__device__ float g_h[NN * CC];                      // 8 MB
__device__ unsigned long long g_topk[NN * TOPK];    // ~1.1 MB
__device__ float g_sum;

// ------ Eigen/MLIR fast-tanh, FMA variant (clamp 7.99881172180175781) ------
// Exact replica of the mlir math-polynomial-approximation / Eigen ptanh_float
// FMA path that XLA:CPU emits: clamp, x2, two Horner FMA chains, IEEE divide,
// |x| < 0.0004 passthrough. Bit-identical for bit-identical input.
// (Resubmission: R6 failed with cudaErrorSystemNotReady — infra, kernel never ran.)
__device__ __forceinline__ float ftanh(float x) {
    const float kMax = 7.99881172180175781f;
    float xc = fminf(fmaxf(x, -kMax), kMax);
    float x2 = __fmul_rn(xc, xc);
    float p = __fmaf_rn(x2, -2.76076847742355e-16f, 2.00018790482477e-13f);
    p = __fmaf_rn(x2, p, -8.60467152213735e-11f);
    p = __fmaf_rn(x2, p,  5.12229709037114e-08f);
    p = __fmaf_rn(x2, p,  1.48572235717979e-05f);
    p = __fmaf_rn(x2, p,  6.37261928875436e-04f);
    p = __fmaf_rn(x2, p,  4.89352455891786e-03f);
    p = __fmul_rn(xc, p);
    float q = __fmaf_rn(x2, 1.19825839466702e-06f, 1.18534705686654e-04f);
    q = __fmaf_rn(x2, q, 2.26843463243900e-03f);
    q = __fmaf_rn(x2, q, 4.89352518554385e-03f);
    float r = __fdiv_rn(p, q);
    return (fabsf(x) < 0.0004f) ? x : r;
}

// ---------------- K1: h = x @ lin  (M=8192, N=256, K=256) -------------------
__global__ void __launch_bounds__(256) k1_gemm(const float* __restrict__ x,
                                               const float* __restrict__ lin) {
    __shared__ float As[16][64];   // As[k][m]
    __shared__ float Bs[16][64];   // Bs[k][n]
    int bm = blockIdx.x, bn = blockIdx.y;
    int tid = threadIdx.x;
    int tx = tid & 15, ty = tid >> 4;
    int ar = tid >> 2, ak = (tid & 3) * 4;    // A load: row, k-base
    int bk = tid >> 4, bc = (tid & 15) * 4;   // B load: k, col-base

    float acc[4][4];
#pragma unroll
    for (int i = 0; i < 4; i++)
#pragma unroll
        for (int j = 0; j < 4; j++) acc[i][j] = 0.f;

    for (int kt = 0; kt < CC; kt += 16) {
        float4 av = *(const float4*)(x + (size_t)(bm * 64 + ar) * CC + kt + ak);
        float4 bv = *(const float4*)(lin + (size_t)(kt + bk) * CC + bn * 64 + bc);
        __syncthreads();
        As[ak + 0][ar] = av.x; As[ak + 1][ar] = av.y;
        As[ak + 2][ar] = av.z; As[ak + 3][ar] = av.w;
        *(float4*)&Bs[bk][bc] = bv;
        __syncthreads();
#pragma unroll
        for (int kk = 0; kk < 16; kk++) {
            float a[4], b[4];
#pragma unroll
            for (int i = 0; i < 4; i++) a[i] = As[kk][ty * 4 + i];
#pragma unroll
            for (int j = 0; j < 4; j++) b[j] = Bs[kk][tx * 4 + j];
#pragma unroll
            for (int i = 0; i < 4; i++)
#pragma unroll
                for (int j = 0; j < 4; j++) acc[i][j] = __fmaf_rn(a[i], b[j], acc[i][j]);
        }
    }
#pragma unroll
    for (int i = 0; i < 4; i++) {
        float4 o = make_float4(acc[i][0], acc[i][1], acc[i][2], acc[i][3]);
        *(float4*)(g_h + (size_t)(bm * 64 + ty * 4 + i) * CC + bn * 64 + tx * 4) = o;
    }
}

// ------- K2: A = relu(ftanh(h h^T)); symmetric — upper tiles only -----------
__global__ void __launch_bounds__(256) k2_syrk(float* __restrict__ A) {
    __shared__ float As[8][128];
    __shared__ float Bs[8][128];
    int t = blockIdx.x, bi = 0;
    while (t >= 64 - bi) { t -= 64 - bi; ++bi; }
    int bj = bi + t;

    int tid = threadIdx.x;
    int tx = tid & 15, ty = tid >> 4;
    int lr = tid >> 1, lk = (tid & 1) * 4;
    const float* ap = g_h + (size_t)(bi * 128 + lr) * CC + lk;
    const float* bp = g_h + (size_t)(bj * 128 + lr) * CC + lk;

    float acc[8][8];
#pragma unroll
    for (int i = 0; i < 8; i++)
#pragma unroll
        for (int j = 0; j < 8; j++) acc[i][j] = 0.f;

    for (int kt = 0; kt < CC; kt += 8) {
        float4 av = *(const float4*)(ap + kt);
        float4 bv = *(const float4*)(bp + kt);
        __syncthreads();
        As[lk + 0][lr] = av.x; As[lk + 1][lr] = av.y;
        As[lk + 2][lr] = av.z; As[lk + 3][lr] = av.w;
        Bs[lk + 0][lr] = bv.x; Bs[lk + 1][lr] = bv.y;
        Bs[lk + 2][lr] = bv.z; Bs[lk + 3][lr] = bv.w;
        __syncthreads();
#pragma unroll
        for (int kk = 0; kk < 8; kk++) {
            float a[8], b[8];
#pragma unroll
            for (int i = 0; i < 8; i++) a[i] = As[kk][ty * 8 + i];
#pragma unroll
            for (int j = 0; j < 8; j++) b[j] = Bs[kk][tx * 8 + j];
#pragma unroll
            for (int i = 0; i < 8; i++)
#pragma unroll
                for (int j = 0; j < 8; j++) acc[i][j] = __fmaf_rn(a[i], b[j], acc[i][j]);
        }
    }
    // fused activation: relu(ftanh(.)) — exact reference tanh replica
#pragma unroll
    for (int i = 0; i < 8; i++)
#pragma unroll
        for (int j = 0; j < 8; j++) acc[i][j] = fmaxf(ftanh(acc[i][j]), 0.0f);

    int r0 = bi * 128 + ty * 8, c0 = bj * 128 + tx * 8;
#pragma unroll
    for (int i = 0; i < 8; i++) {
        float* p = A + (size_t)(r0 + i) * NN + c0;
        *(float4*)p       = make_float4(acc[i][0], acc[i][1], acc[i][2], acc[i][3]);
        *(float4*)(p + 4) = make_float4(acc[i][4], acc[i][5], acc[i][6], acc[i][7]);
    }
    if (bi != bj) {
#pragma unroll
        for (int j = 0; j < 8; j++) {
            float* p = A + (size_t)(c0 + j) * NN + r0;
            *(float4*)p       = make_float4(acc[0][j], acc[1][j], acc[2][j], acc[3][j]);
            *(float4*)(p + 4) = make_float4(acc[4][j], acc[5][j], acc[6][j], acc[7][j]);
        }
    }
}

// ---------------- K3: per-row top-17, ties -> smaller index -----------------
__device__ __forceinline__ void tk_insert(unsigned long long (&loc)[TOPK],
                                          unsigned long long key) {
    if (key > loc[TOPK - 1]) {
        loc[TOPK - 1] = key;
#pragma unroll
        for (int q = TOPK - 1; q > 0; q--) {
            unsigned long long a = loc[q - 1], b = loc[q];
            if (b > a) { loc[q - 1] = b; loc[q] = a; }
        }
    }
}

__device__ __forceinline__ unsigned long long warpmax_u64(unsigned long long v) {
#pragma unroll
    for (int off = 16; off; off >>= 1) {
        unsigned long long o = __shfl_xor_sync(0xffffffffu, v, off);
        if (o > v) v = o;
    }
    return v;
}

__global__ void __launch_bounds__(256) k3_topk(const float* __restrict__ A) {
    int row = blockIdx.x;
    int tid = threadIdx.x;
    unsigned long long loc[TOPK];
#pragma unroll
    for (int q = 0; q < TOPK; q++) loc[q] = 0ull;

    const float4* rp = (const float4*)(A + (size_t)row * NN);
#pragma unroll
    for (int it = 0; it < NN / 4 / 256; it++) {
        int c4 = tid + it * 256;
        float4 v = rp[c4];
        int col = c4 * 4;
        tk_insert(loc, ((unsigned long long)__float_as_uint(v.x) << 32) | (0xFFFFFFFFu - (unsigned)(col + 0)));
        tk_insert(loc, ((unsigned long long)__float_as_uint(v.y) << 32) | (0xFFFFFFFFu - (unsigned)(col + 1)));
        tk_insert(loc, ((unsigned long long)__float_as_uint(v.z) << 32) | (0xFFFFFFFFu - (unsigned)(col + 2)));
        tk_insert(loc, ((unsigned long long)__float_as_uint(v.w) << 32) | (0xFFFFFFFFu - (unsigned)(col + 3)));
    }

    __shared__ unsigned long long wl[8][TOPK];
    int lane = tid & 31, wp = tid >> 5;
    for (int it = 0; it < TOPK; it++) {
        unsigned long long best = warpmax_u64(loc[0]);
        unsigned m = __ballot_sync(0xffffffffu, loc[0] == best);
        if (lane == (__ffs(m) - 1)) {
#pragma unroll
            for (int q = 0; q < TOPK - 1; q++) loc[q] = loc[q + 1];
            loc[TOPK - 1] = 0ull;
        }
        if (lane == 0) wl[wp][it] = best;
    }
    __syncthreads();
    if (wp == 0) {
        int p = 0;
        for (int it = 0; it < TOPK; it++) {
            unsigned long long cand = (lane < 8) ? wl[lane][p] : 0ull;
            unsigned long long best = warpmax_u64(cand);
            unsigned m = __ballot_sync(0xffffffffu, (cand == best) && (lane < 8));
            if (lane == (__ffs(m) - 1)) p++;
            if (lane == 0) g_topk[row * TOPK + it] = best;
        }
    }
}

// ---------------- K4: sum of selected non-diagonal values -------------------
__global__ void k4_zero_sum() { g_sum = 0.f; }

__global__ void __launch_bounds__(256) k4_sum() {
    int i = blockIdx.x * blockDim.x + threadIdx.x;
    int stride = gridDim.x * blockDim.x;
    float s = 0.f;
    for (int e = i; e < NN * TOPK; e += stride) {
        unsigned long long key = g_topk[e];
        int row = e / TOPK;
        unsigned col = 0xFFFFFFFFu - (unsigned)(key & 0xFFFFFFFFull);
        float v = __uint_as_float((unsigned)(key >> 32));
        if (col < NN && col != (unsigned)row) s += v;
    }
    __shared__ float sh[256];
    sh[threadIdx.x] = s;
    __syncthreads();
    for (int st = 128; st; st >>= 1) {
        if (threadIdx.x < st) sh[threadIdx.x] += sh[threadIdx.x + st];
        __syncthreads();
    }
    if (threadIdx.x == 0) atomicAdd(&g_sum, sh[0]);
}

// ---------------- K5: zero-fill output --------------------------------------
__global__ void __launch_bounds__(256) k5_zero(float4* __restrict__ out) {
    size_t i = (size_t)blockIdx.x * blockDim.x + threadIdx.x;
    size_t stride = (size_t)gridDim.x * blockDim.x;
    float4 z = make_float4(0.f, 0.f, 0.f, 0.f);
    for (; i < (size_t)NN * NN / 4; i += stride) out[i] = z;
}

// ---------------- K6: scatter selected entries / mean -----------------------
__global__ void __launch_bounds__(256) k6_scatter(float* __restrict__ out) {
    int row = blockIdx.x * 8 + (threadIdx.x >> 5);
    int lane = threadIdx.x & 31;
    float mean = g_sum / (float)(KNN * NN);
    if (lane < TOPK) {
        unsigned long long key = g_topk[row * TOPK + lane];
        unsigned col = 0xFFFFFFFFu - (unsigned)(key & 0xFFFFFFFFull);
        float v = __uint_as_float((unsigned)(key >> 32));
        if (col < NN && col != (unsigned)row)
            out[(size_t)row * NN + col] = __fdiv_rn(v, mean);
    }
}

// ---------------- launch ----------------------------------------------------
extern "C" void kernel_launch(void* const* d_in, const int* in_sizes, int n_in,
                              void* d_out, int out_size) {
    const float* x   = (const float*)d_in[0];
    const float* lin = (const float*)d_in[1];
    // defensive: x is the 8192x256 tensor, lin the 256x256 one
    if (n_in >= 2 && in_sizes[0] < in_sizes[1]) {
        const float* tmp = x; x = lin; lin = tmp;
    }
    float* out = (float*)d_out;

    k1_gemm<<<dim3(128, 4), 256>>>(x, lin);
    k2_syrk<<<2080, 256>>>(out);
    k3_topk<<<8192, 256>>>(out);
    k4_zero_sum<<<1, 1>>>();
    k4_sum<<<128, 256>>>();
    k5_zero<<<16384, 256>>>((float4*)out);
    k6_scatter<<<1024, 256>>>(out);
}

// round 9
// speedup vs baseline: 4.7767x; 4.7767x over previous
#include <cuda_runtime.h>
#include <cstdint>

#define NN 8192
#define CC 256
#define TOPK 17
#define KNN 16
#define PRE 512

__device__ float g_h[NN * CC];
__device__ float g_Apre[NN * PRE];                  // 16 MB prefix values
__device__ unsigned long long g_topk[NN * TOPK];
__device__ float g_sum;
__device__ int g_bad[NN];
__device__ int g_anomaly;
__device__ unsigned g_Vp_bits;

// Eigen/MLIR fast-tanh FMA variant — bit-exact vs reference (proven R7).
__device__ __forceinline__ float ftanh(float x) {
    const float kMax = 7.99881172180175781f;
    float xc = fminf(fmaxf(x, -kMax), kMax);
    float x2 = __fmul_rn(xc, xc);
    float p = __fmaf_rn(x2, -2.76076847742355e-16f, 2.00018790482477e-13f);
    p = __fmaf_rn(x2, p, -8.60467152213735e-11f);
    p = __fmaf_rn(x2, p,  5.12229709037114e-08f);
    p = __fmaf_rn(x2, p,  1.48572235717979e-05f);
    p = __fmaf_rn(x2, p,  6.37261928875436e-04f);
    p = __fmaf_rn(x2, p,  4.89352455891786e-03f);
    p = __fmul_rn(xc, p);
    float q = __fmaf_rn(x2, 1.19825839466702e-06f, 1.18534705686654e-04f);
    q = __fmaf_rn(x2, q, 2.26843463243900e-03f);
    q = __fmaf_rn(x2, q, 4.89352518554385e-03f);
    float r = __fdiv_rn(p, q);
    return (fabsf(x) < 0.0004f) ? x : r;
}
__device__ __forceinline__ float act(float x) { return fmaxf(ftanh(x), 0.0f); }

__global__ void k0_init() { g_anomaly = 0; g_Vp_bits = __float_as_uint(act(8.0f)); }

// Verify: no fp32 x in [2.0, kMax) has act(x) > V_p. Below 2.0, tanh<=0.9641.
__global__ void __launch_bounds__(256) kver() {
    unsigned lo = __float_as_uint(2.0f);
    unsigned hi = __float_as_uint(7.99881172180175781f);
    float Vp = act(8.0f);
    unsigned i = lo + blockIdx.x * blockDim.x + threadIdx.x;
    unsigned stride = gridDim.x * blockDim.x;
    bool bad = false;
    for (; i < hi; i += stride) bad |= (act(__uint_as_float(i)) > Vp);
    if (__syncthreads_or(bad) && threadIdx.x == 0) g_anomaly = 1;
}

// K1: h = x @ lin
__global__ void __launch_bounds__(256) k1_gemm(const float* __restrict__ x,
                                               const float* __restrict__ lin) {
    __shared__ float As[16][64], Bs[16][64];
    int bm = blockIdx.x, bn = blockIdx.y, tid = threadIdx.x;
    int tx = tid & 15, ty = tid >> 4;
    int ar = tid >> 2, ak = (tid & 3) * 4;
    int bk = tid >> 4, bc = (tid & 15) * 4;
    float acc[4][4];
#pragma unroll
    for (int i = 0; i < 4; i++)
#pragma unroll
        for (int j = 0; j < 4; j++) acc[i][j] = 0.f;
    for (int kt = 0; kt < CC; kt += 16) {
        float4 av = *(const float4*)(x + (size_t)(bm * 64 + ar) * CC + kt + ak);
        float4 bv = *(const float4*)(lin + (size_t)(kt + bk) * CC + bn * 64 + bc);
        __syncthreads();
        As[ak + 0][ar] = av.x; As[ak + 1][ar] = av.y;
        As[ak + 2][ar] = av.z; As[ak + 3][ar] = av.w;
        *(float4*)&Bs[bk][bc] = bv;
        __syncthreads();
#pragma unroll
        for (int kk = 0; kk < 16; kk++) {
            float a[4], b[4];
#pragma unroll
            for (int i = 0; i < 4; i++) a[i] = As[kk][ty * 4 + i];
#pragma unroll
            for (int j = 0; j < 4; j++) b[j] = Bs[kk][tx * 4 + j];
#pragma unroll
            for (int i = 0; i < 4; i++)
#pragma unroll
                for (int j = 0; j < 4; j++) acc[i][j] = __fmaf_rn(a[i], b[j], acc[i][j]);
        }
    }
#pragma unroll
    for (int i = 0; i < 4; i++)
        *(float4*)(g_h + (size_t)(bm * 64 + ty * 4 + i) * CC + bn * 64 + tx * 4) =
            make_float4(acc[i][0], acc[i][1], acc[i][2], acc[i][3]);
}

// Shared 128x128 tile body (sequential-k FMA chains, identical bits to R7 k2)
__device__ __forceinline__ void tile_dots(int bi, int bj, float (&accr)[8][8]) {
    __shared__ float As[8][128], Bs[8][128];
    int tid = threadIdx.x;
    int tx = tid & 15, ty = tid >> 4;
    int lr = tid >> 1, lk = (tid & 1) * 4;
    const float* ap = g_h + (size_t)(bi * 128 + lr) * CC + lk;
    const float* bp = g_h + (size_t)(bj * 128 + lr) * CC + lk;
#pragma unroll
    for (int i = 0; i < 8; i++)
#pragma unroll
        for (int j = 0; j < 8; j++) accr[i][j] = 0.f;
    for (int kt = 0; kt < CC; kt += 8) {
        float4 av = *(const float4*)(ap + kt);
        float4 bv = *(const float4*)(bp + kt);
        __syncthreads();
        As[lk + 0][lr] = av.x; As[lk + 1][lr] = av.y;
        As[lk + 2][lr] = av.z; As[lk + 3][lr] = av.w;
        Bs[lk + 0][lr] = bv.x; Bs[lk + 1][lr] = bv.y;
        Bs[lk + 2][lr] = bv.z; Bs[lk + 3][lr] = bv.w;
        __syncthreads();
#pragma unroll
        for (int kk = 0; kk < 8; kk++) {
            float a[8], b[8];
#pragma unroll
            for (int i = 0; i < 8; i++) a[i] = As[kk][ty * 8 + i];
#pragma unroll
            for (int j = 0; j < 8; j++) b[j] = Bs[kk][tx * 8 + j];
#pragma unroll
            for (int i = 0; i < 8; i++)
#pragma unroll
                for (int j = 0; j < 8; j++) accr[i][j] = __fmaf_rn(a[i], b[j], accr[i][j]);
        }
    }
}

// K2p: prefix panel — rows all, cols [0, 512)
__global__ void __launch_bounds__(256) k2p_prefix() {
    int bj = blockIdx.x, bi = blockIdx.y;     // bj in [0,4), bi in [0,64)
    float acc[8][8];
    tile_dots(bi, bj, acc);
    int tid = threadIdx.x, tx = tid & 15, ty = tid >> 4;
    int r0 = bi * 128 + ty * 8, c0 = bj * 128 + tx * 8;
#pragma unroll
    for (int i = 0; i < 8; i++) {
#pragma unroll
        for (int j = 0; j < 8; j++) acc[i][j] = act(acc[i][j]);
        float* p = g_Apre + (size_t)(r0 + i) * PRE + c0;
        *(float4*)p       = make_float4(acc[i][0], acc[i][1], acc[i][2], acc[i][3]);
        *(float4*)(p + 4) = make_float4(acc[i][4], acc[i][5], acc[i][6], acc[i][7]);
    }
}

// kscan: first 17 prefix cols with bits == V_p; flag rows with fewer.
__global__ void __launch_bounds__(256) kscan() {
    int row = blockIdx.x * 8 + (threadIdx.x >> 5);
    int lane = threadIdx.x & 31;
    unsigned vp = g_Vp_bits;
    int cnt = 0;
    for (int c = 0; c < PRE / 32 && cnt < TOPK; c++) {
        float v = g_Apre[(size_t)row * PRE + c * 32 + lane];
        unsigned b = __ballot_sync(0xffffffffu, __float_as_uint(v) == vp);
        if (lane == 0) {
            while (b && cnt < TOPK) {
                int l = __ffs(b) - 1; b &= b - 1;
                unsigned col = c * 32 + l;
                g_topk[row * TOPK + cnt] =
                    ((unsigned long long)vp << 32) | (0xFFFFFFFFu - col);
                cnt++;
            }
        }
        cnt = __shfl_sync(0xffffffffu, cnt, 0);
    }
    if (lane == 0) g_bad[row] = (cnt < TOPK) ? 1 : 0;
}

__device__ __forceinline__ void tk_insert(unsigned long long (&loc)[TOPK],
                                          unsigned long long key) {
    if (key > loc[TOPK - 1]) {
        loc[TOPK - 1] = key;
#pragma unroll
        for (int q = TOPK - 1; q > 0; q--) {
            unsigned long long a = loc[q - 1], b = loc[q];
            if (b > a) { loc[q - 1] = b; loc[q] = a; }
        }
    }
}
__device__ __forceinline__ unsigned long long warpmax_u64(unsigned long long v) {
#pragma unroll
    for (int off = 16; off; off >>= 1) {
        unsigned long long o = __shfl_xor_sync(0xffffffffu, v, off);
        if (o > v) v = o;
    }
    return v;
}
__device__ void topk_merge_write(unsigned long long (&loc)[TOPK], int row) {
    __shared__ unsigned long long wl[8][TOPK];
    int lane = threadIdx.x & 31, wp = threadIdx.x >> 5;
    for (int it = 0; it < TOPK; it++) {
        unsigned long long best = warpmax_u64(loc[0]);
        unsigned m = __ballot_sync(0xffffffffu, loc[0] == best);
        if (lane == (__ffs(m) - 1)) {
#pragma unroll
            for (int q = 0; q < TOPK - 1; q++) loc[q] = loc[q + 1];
            loc[TOPK - 1] = 0ull;
        }
        if (lane == 0) wl[wp][it] = best;
    }
    __syncthreads();
    if (wp == 0) {
        int p = 0;
        for (int it = 0; it < TOPK; it++) {
            unsigned long long cand = (lane < 8) ? wl[lane][p] : 0ull;
            unsigned long long best = warpmax_u64(cand);
            unsigned m = __ballot_sync(0xffffffffu, (cand == best) && (lane < 8));
            if (lane == (__ffs(m) - 1)) p++;
            if (lane == 0) g_topk[row * TOPK + it] = best;
        }
    }
}

// kbad: exact full-row recompute for flagged rows (rare/never)
__global__ void __launch_bounds__(256) kbad() {
    int row = blockIdx.x;
    if (g_anomaly || !g_bad[row]) return;
    __shared__ float hr[CC];
    int tid = threadIdx.x;
    hr[tid] = g_h[(size_t)row * CC + tid];
    __syncthreads();
    unsigned long long loc[TOPK];
#pragma unroll
    for (int q = 0; q < TOPK; q++) loc[q] = 0ull;
    for (int j = tid; j < NN; j += 256) {
        const float4* bp = (const float4*)(g_h + (size_t)j * CC);
        float accv = 0.f;
        for (int k4i = 0; k4i < CC / 4; k4i++) {
            float4 b = bp[k4i];
            accv = __fmaf_rn(hr[k4i * 4 + 0], b.x, accv);
            accv = __fmaf_rn(hr[k4i * 4 + 1], b.y, accv);
            accv = __fmaf_rn(hr[k4i * 4 + 2], b.z, accv);
            accv = __fmaf_rn(hr[k4i * 4 + 3], b.w, accv);
        }
        float v = act(accv);
        tk_insert(loc, ((unsigned long long)__float_as_uint(v) << 32) |
                       (0xFFFFFFFFu - (unsigned)j));
    }
    topk_merge_write(loc, row);
}

// Gated fallback: full exact SYRK + topk (only if tanh anomaly detected)
__global__ void __launch_bounds__(256) k2_syrk(float* __restrict__ A) {
    if (!g_anomaly) return;
    int t = blockIdx.x, bi = 0;
    while (t >= 64 - bi) { t -= 64 - bi; ++bi; }
    int bj = bi + t;
    float acc[8][8];
    tile_dots(bi, bj, acc);
    int tid = threadIdx.x, tx = tid & 15, ty = tid >> 4;
#pragma unroll
    for (int i = 0; i < 8; i++)
#pragma unroll
        for (int j = 0; j < 8; j++) acc[i][j] = act(acc[i][j]);
    int r0 = bi * 128 + ty * 8, c0 = bj * 128 + tx * 8;
#pragma unroll
    for (int i = 0; i < 8; i++) {
        float* p = A + (size_t)(r0 + i) * NN + c0;
        *(float4*)p       = make_float4(acc[i][0], acc[i][1], acc[i][2], acc[i][3]);
        *(float4*)(p + 4) = make_float4(acc[i][4], acc[i][5], acc[i][6], acc[i][7]);
    }
    if (bi != bj) {
#pragma unroll
        for (int j = 0; j < 8; j++) {
            float* p = A + (size_t)(c0 + j) * NN + r0;
            *(float4*)p       = make_float4(acc[0][j], acc[1][j], acc[2][j], acc[3][j]);
            *(float4*)(p + 4) = make_float4(acc[4][j], acc[5][j], acc[6][j], acc[7][j]);
        }
    }
}

__global__ void __launch_bounds__(256) k3_topk(const float* __restrict__ A) {
    if (!g_anomaly) return;
    int row = blockIdx.x, tid = threadIdx.x;
    unsigned long long loc[TOPK];
#pragma unroll
    for (int q = 0; q < TOPK; q++) loc[q] = 0ull;
    const float4* rp = (const float4*)(A + (size_t)row * NN);
#pragma unroll
    for (int it = 0; it < NN / 4 / 256; it++) {
        int c4 = tid + it * 256;
        float4 v = rp[c4];
        int col = c4 * 4;
        tk_insert(loc, ((unsigned long long)__float_as_uint(v.x) << 32) | (0xFFFFFFFFu - (unsigned)(col + 0)));
        tk_insert(loc, ((unsigned long long)__float_as_uint(v.y) << 32) | (0xFFFFFFFFu - (unsigned)(col + 1)));
        tk_insert(loc, ((unsigned long long)__float_as_uint(v.z) << 32) | (0xFFFFFFFFu - (unsigned)(col + 2)));
        tk_insert(loc, ((unsigned long long)__float_as_uint(v.w) << 32) | (0xFFFFFFFFu - (unsigned)(col + 3)));
    }
    topk_merge_write(loc, row);
}

__global__ void k4_zero_sum() { g_sum = 0.f; }
__global__ void __launch_bounds__(256) k4_sum() {
    int i = blockIdx.x * blockDim.x + threadIdx.x;
    int stride = gridDim.x * blockDim.x;
    float s = 0.f;
    for (int e = i; e < NN * TOPK; e += stride) {
        unsigned long long key = g_topk[e];
        int row = e / TOPK;
        unsigned col = 0xFFFFFFFFu - (unsigned)(key & 0xFFFFFFFFull);
        float v = __uint_as_float((unsigned)(key >> 32));
        if (col < NN && col != (unsigned)row) s += v;
    }
    __shared__ float sh[256];
    sh[threadIdx.x] = s;
    __syncthreads();
    for (int st = 128; st; st >>= 1) {
        if (threadIdx.x < st) sh[threadIdx.x] += sh[threadIdx.x + st];
        __syncthreads();
    }
    if (threadIdx.x == 0) atomicAdd(&g_sum, sh[0]);
}

__global__ void __launch_bounds__(256) k5_zero(float4* __restrict__ out) {
    size_t i = (size_t)blockIdx.x * blockDim.x + threadIdx.x;
    size_t stride = (size_t)gridDim.x * blockDim.x;
    float4 z = make_float4(0.f, 0.f, 0.f, 0.f);
    for (; i < (size_t)NN * NN / 4; i += stride) out[i] = z;
}

__global__ void __launch_bounds__(256) k6_scatter(float* __restrict__ out) {
    int row = blockIdx.x * 8 + (threadIdx.x >> 5);
    int lane = threadIdx.x & 31;
    float mean = g_sum / (float)(KNN * NN);
    if (lane < TOPK) {
        unsigned long long key = g_topk[row * TOPK + lane];
        unsigned col = 0xFFFFFFFFu - (unsigned)(key & 0xFFFFFFFFull);
        float v = __uint_as_float((unsigned)(key >> 32));
        if (col < NN && col != (unsigned)row)
            out[(size_t)row * NN + col] = __fdiv_rn(v, mean);
    }
}

extern "C" void kernel_launch(void* const* d_in, const int* in_sizes, int n_in,
                              void* d_out, int out_size) {
    const float* x   = (const float*)d_in[0];
    const float* lin = (const float*)d_in[1];
    if (n_in >= 2 && in_sizes[0] < in_sizes[1]) {
        const float* tmp = x; x = lin; lin = tmp;
    }
    float* out = (float*)d_out;

    k0_init<<<1, 1>>>();
    k1_gemm<<<dim3(128, 4), 256>>>(x, lin);
    kver<<<256, 256>>>();
    k2p_prefix<<<dim3(4, 64), 256>>>();
    kscan<<<1024, 256>>>();
    kbad<<<8192, 256>>>();
    k2_syrk<<<2080, 256>>>(out);     // no-op unless anomaly
    k3_topk<<<8192, 256>>>(out);     // no-op unless anomaly
    k4_zero_sum<<<1, 1>>>();
    k4_sum<<<128, 256>>>();
    k5_zero<<<16384, 256>>>((float4*)out);
    k6_scatter<<<1024, 256>>>(out);
}

// round 12
// speedup vs baseline: 5.6735x; 1.1877x over previous
#include <cuda_runtime.h>
#include <cstdint>

#define NN 8192
#define CC 256
#define TOPK 17
#define KNN 16
#define PRE 256

__device__ float g_h[NN * CC];
__device__ float g_Apre[NN * PRE];                  // 8 MB prefix values
__device__ unsigned long long g_topk[NN * TOPK];
__device__ float g_sum;
__device__ int g_bad[NN];
__device__ int g_anomaly;
__device__ unsigned g_Vp_bits;

// Eigen/MLIR fast-tanh FMA variant — bit-exact vs reference (proven R7/R9).
__device__ __forceinline__ float ftanh(float x) {
    const float kMax = 7.99881172180175781f;
    float xc = fminf(fmaxf(x, -kMax), kMax);
    float x2 = __fmul_rn(xc, xc);
    float p = __fmaf_rn(x2, -2.76076847742355e-16f, 2.00018790482477e-13f);
    p = __fmaf_rn(x2, p, -8.60467152213735e-11f);
    p = __fmaf_rn(x2, p,  5.12229709037114e-08f);
    p = __fmaf_rn(x2, p,  1.48572235717979e-05f);
    p = __fmaf_rn(x2, p,  6.37261928875436e-04f);
    p = __fmaf_rn(x2, p,  4.89352455891786e-03f);
    p = __fmul_rn(xc, p);
    float q = __fmaf_rn(x2, 1.19825839466702e-06f, 1.18534705686654e-04f);
    q = __fmaf_rn(x2, q, 2.26843463243900e-03f);
    q = __fmaf_rn(x2, q, 4.89352518554385e-03f);
    float r = __fdiv_rn(p, q);
    return (fabsf(x) < 0.0004f) ? x : r;
}
__device__ __forceinline__ float act(float x) { return fmaxf(ftanh(x), 0.0f); }

__global__ void k0_init() { g_anomaly = 0; g_Vp_bits = __float_as_uint(act(8.0f)); }

// Verify: no fp32 x in [2.0, kMax) has act(x) > V_p. Below 2.0, tanh<=0.9641.
__global__ void __launch_bounds__(256) kver() {
    unsigned lo = __float_as_uint(2.0f);
    unsigned hi = __float_as_uint(7.99881172180175781f);
    float Vp = act(8.0f);
    unsigned i = lo + blockIdx.x * blockDim.x + threadIdx.x;
    unsigned stride = gridDim.x * blockDim.x;
    bool bad = false;
    for (; i < hi; i += stride) bad |= (act(__uint_as_float(i)) > Vp);
    if (__syncthreads_or(bad) && threadIdx.x == 0) g_anomaly = 1;
}

// K1: h = x @ lin (unchanged — proven)
__global__ void __launch_bounds__(256) k1_gemm(const float* __restrict__ x,
                                               const float* __restrict__ lin) {
    __shared__ float As[16][64], Bs[16][64];
    int bm = blockIdx.x, bn = blockIdx.y, tid = threadIdx.x;
    int tx = tid & 15, ty = tid >> 4;
    int ar = tid >> 2, ak = (tid & 3) * 4;
    int bk = tid >> 4, bc = (tid & 15) * 4;
    float acc[4][4];
#pragma unroll
    for (int i = 0; i < 4; i++)
#pragma unroll
        for (int j = 0; j < 4; j++) acc[i][j] = 0.f;
    for (int kt = 0; kt < CC; kt += 16) {
        float4 av = *(const float4*)(x + (size_t)(bm * 64 + ar) * CC + kt + ak);
        float4 bv = *(const float4*)(lin + (size_t)(kt + bk) * CC + bn * 64 + bc);
        __syncthreads();
        As[ak + 0][ar] = av.x; As[ak + 1][ar] = av.y;
        As[ak + 2][ar] = av.z; As[ak + 3][ar] = av.w;
        *(float4*)&Bs[bk][bc] = bv;
        __syncthreads();
#pragma unroll
        for (int kk = 0; kk < 16; kk++) {
            float a[4], b[4];
#pragma unroll
            for (int i = 0; i < 4; i++) a[i] = As[kk][ty * 4 + i];
#pragma unroll
            for (int j = 0; j < 4; j++) b[j] = Bs[kk][tx * 4 + j];
#pragma unroll
            for (int i = 0; i < 4; i++)
#pragma unroll
                for (int j = 0; j < 4; j++) acc[i][j] = __fmaf_rn(a[i], b[j], acc[i][j]);
        }
    }
#pragma unroll
    for (int i = 0; i < 4; i++)
        *(float4*)(g_h + (size_t)(bm * 64 + ty * 4 + i) * CC + bn * 64 + tx * 4) =
            make_float4(acc[i][0], acc[i][1], acc[i][2], acc[i][3]);
}

// K2p: exact fp32 prefix panel — all rows x cols [0, PRE). K-step 16.
// Accumulation k-order remains strictly sequential 0..255 => dot bits
// identical to R7/R9 (which passed with rel_err = 0.0).
__global__ void __launch_bounds__(256) k2p_prefix() {
    __shared__ float As[16][128], Bs[16][128];
    int bj = blockIdx.x, bi = blockIdx.y;     // bj in [0,2), bi in [0,64)
    int tid = threadIdx.x;
    int tx = tid & 15, ty = tid >> 4;
    int lr = tid >> 1, lk = (tid & 1) * 8;
    const float* ap = g_h + (size_t)(bi * 128 + lr) * CC + lk;
    const float* bp = g_h + (size_t)(bj * 128 + lr) * CC + lk;

    float acc[8][8];
#pragma unroll
    for (int i = 0; i < 8; i++)
#pragma unroll
        for (int j = 0; j < 8; j++) acc[i][j] = 0.f;

    for (int kt = 0; kt < CC; kt += 16) {
        float4 a0 = *(const float4*)(ap + kt);
        float4 a1 = *(const float4*)(ap + kt + 4);
        float4 b0 = *(const float4*)(bp + kt);
        float4 b1 = *(const float4*)(bp + kt + 4);
        __syncthreads();
        As[lk + 0][lr] = a0.x; As[lk + 1][lr] = a0.y;
        As[lk + 2][lr] = a0.z; As[lk + 3][lr] = a0.w;
        As[lk + 4][lr] = a1.x; As[lk + 5][lr] = a1.y;
        As[lk + 6][lr] = a1.z; As[lk + 7][lr] = a1.w;
        Bs[lk + 0][lr] = b0.x; Bs[lk + 1][lr] = b0.y;
        Bs[lk + 2][lr] = b0.z; Bs[lk + 3][lr] = b0.w;
        Bs[lk + 4][lr] = b1.x; Bs[lk + 5][lr] = b1.y;
        Bs[lk + 6][lr] = b1.z; Bs[lk + 7][lr] = b1.w;
        __syncthreads();
#pragma unroll
        for (int kk = 0; kk < 16; kk++) {
            float a[8], b[8];
#pragma unroll
            for (int i = 0; i < 8; i++) a[i] = As[kk][ty * 8 + i];
#pragma unroll
            for (int j = 0; j < 8; j++) b[j] = Bs[kk][tx * 8 + j];
#pragma unroll
            for (int i = 0; i < 8; i++)
#pragma unroll
                for (int j = 0; j < 8; j++) acc[i][j] = __fmaf_rn(a[i], b[j], acc[i][j]);
        }
    }
    int r0 = bi * 128 + ty * 8, c0 = bj * 128 + tx * 8;
#pragma unroll
    for (int i = 0; i < 8; i++) {
#pragma unroll
        for (int j = 0; j < 8; j++) acc[i][j] = act(acc[i][j]);
        float* p = g_Apre + (size_t)(r0 + i) * PRE + c0;
        *(float4*)p       = make_float4(acc[i][0], acc[i][1], acc[i][2], acc[i][3]);
        *(float4*)(p + 4) = make_float4(acc[i][4], acc[i][5], acc[i][6], acc[i][7]);
    }
}

// kscan: first 17 prefix cols with bits == V_p; flag rows with fewer.
// On tanh anomaly, flag ALL rows -> kbad computes everything exactly.
__global__ void __launch_bounds__(256) kscan() {
    int row = blockIdx.x * 8 + (threadIdx.x >> 5);
    int lane = threadIdx.x & 31;
    unsigned vp = g_Vp_bits;
    int an = g_anomaly;
    int cnt = 0;
    for (int c = 0; c < PRE / 32 && cnt < TOPK; c++) {
        float v = g_Apre[(size_t)row * PRE + c * 32 + lane];
        unsigned b = __ballot_sync(0xffffffffu, __float_as_uint(v) == vp);
        if (lane == 0) {
            while (b && cnt < TOPK) {
                int l = __ffs(b) - 1; b &= b - 1;
                unsigned col = c * 32 + l;
                g_topk[row * TOPK + cnt] =
                    ((unsigned long long)vp << 32) | (0xFFFFFFFFu - col);
                cnt++;
            }
        }
        cnt = __shfl_sync(0xffffffffu, cnt, 0);
    }
    if (lane == 0) g_bad[row] = (an || cnt < TOPK) ? 1 : 0;
}

__device__ __forceinline__ void tk_insert(unsigned long long (&loc)[TOPK],
                                          unsigned long long key) {
    if (key > loc[TOPK - 1]) {
        loc[TOPK - 1] = key;
#pragma unroll
        for (int q = TOPK - 1; q > 0; q--) {
            unsigned long long a = loc[q - 1], b = loc[q];
            if (b > a) { loc[q - 1] = b; loc[q] = a; }
        }
    }
}
__device__ __forceinline__ unsigned long long warpmax_u64(unsigned long long v) {
#pragma unroll
    for (int off = 16; off; off >>= 1) {
        unsigned long long o = __shfl_xor_sync(0xffffffffu, v, off);
        if (o > v) v = o;
    }
    return v;
}
__device__ void topk_merge_write(unsigned long long (&loc)[TOPK], int row) {
    __shared__ unsigned long long wl[8][TOPK];
    int lane = threadIdx.x & 31, wp = threadIdx.x >> 5;
    for (int it = 0; it < TOPK; it++) {
        unsigned long long best = warpmax_u64(loc[0]);
        unsigned m = __ballot_sync(0xffffffffu, loc[0] == best);
        if (lane == (__ffs(m) - 1)) {
#pragma unroll
            for (int q = 0; q < TOPK - 1; q++) loc[q] = loc[q + 1];
            loc[TOPK - 1] = 0ull;
        }
        if (lane == 0) wl[wp][it] = best;
    }
    __syncthreads();
    if (wp == 0) {
        int p = 0;
        for (int it = 0; it < TOPK; it++) {
            unsigned long long cand = (lane < 8) ? wl[lane][p] : 0ull;
            unsigned long long best = warpmax_u64(cand);
            unsigned m = __ballot_sync(0xffffffffu, (cand == best) && (lane < 8));
            if (lane == (__ffs(m) - 1)) p++;
            if (lane == 0) g_topk[row * TOPK + it] = best;
        }
    }
}

// kbad: exact full-row recompute for flagged rows (rare; all rows on anomaly).
// Same sequential-k fma order as k2p -> identical dot bits.
__global__ void __launch_bounds__(256) kbad() {
    int row = blockIdx.x;
    if (!g_bad[row]) return;
    __shared__ float hr[CC];
    int tid = threadIdx.x;
    hr[tid] = g_h[(size_t)row * CC + tid];
    __syncthreads();
    unsigned long long loc[TOPK];
#pragma unroll
    for (int q = 0; q < TOPK; q++) loc[q] = 0ull;
    for (int j = tid; j < NN; j += 256) {
        const float4* bp = (const float4*)(g_h + (size_t)j * CC);
        float accv = 0.f;
        for (int k4i = 0; k4i < CC / 4; k4i++) {
            float4 b = bp[k4i];
            accv = __fmaf_rn(hr[k4i * 4 + 0], b.x, accv);
            accv = __fmaf_rn(hr[k4i * 4 + 1], b.y, accv);
            accv = __fmaf_rn(hr[k4i * 4 + 2], b.z, accv);
            accv = __fmaf_rn(hr[k4i * 4 + 3], b.w, accv);
        }
        float v = act(accv);
        tk_insert(loc, ((unsigned long long)__float_as_uint(v) << 32) |
                       (0xFFFFFFFFu - (unsigned)j));
    }
    topk_merge_write(loc, row);
}

__global__ void k4_zero_sum() { g_sum = 0.f; }
__global__ void __launch_bounds__(256) k4_sum() {
    int i = blockIdx.x * blockDim.x + threadIdx.x;
    int stride = gridDim.x * blockDim.x;
    float s = 0.f;
    for (int e = i; e < NN * TOPK; e += stride) {
        unsigned long long key = g_topk[e];
        int row = e / TOPK;
        unsigned col = 0xFFFFFFFFu - (unsigned)(key & 0xFFFFFFFFull);
        float v = __uint_as_float((unsigned)(key >> 32));
        if (col < NN && col != (unsigned)row) s += v;
    }
    __shared__ float sh[256];
    sh[threadIdx.x] = s;
    __syncthreads();
    for (int st = 128; st; st >>= 1) {
        if (threadIdx.x < st) sh[threadIdx.x] += sh[threadIdx.x + st];
        __syncthreads();
    }
    if (threadIdx.x == 0) atomicAdd(&g_sum, sh[0]);
}

// kfill: fused zero + scatter. Block b owns rows [b*8, b*8+8): zero them,
// sync, then scatter its own rows' entries. No cross-block dependency.
__global__ void __launch_bounds__(256) kfill(float* __restrict__ out) {
    int r0 = blockIdx.x * 8;
    float4* op = (float4*)(out + (size_t)r0 * NN);
    float4 z = make_float4(0.f, 0.f, 0.f, 0.f);
    // 8 rows * 8192 floats = 16384 float4; 256 threads -> 64 each
#pragma unroll 8
    for (int i = threadIdx.x; i < 8 * NN / 4; i += 256) op[i] = z;
    __syncthreads();
    int wp = threadIdx.x >> 5, lane = threadIdx.x & 31;
    float mean = g_sum / (float)(KNN * NN);
    int row = r0 + wp;
    if (lane < TOPK) {
        unsigned long long key = g_topk[row * TOPK + lane];
        unsigned col = 0xFFFFFFFFu - (unsigned)(key & 0xFFFFFFFFull);
        float v = __uint_as_float((unsigned)(key >> 32));
        if (col < NN && col != (unsigned)row)
            out[(size_t)row * NN + col] = __fdiv_rn(v, mean);
    }
}

extern "C" void kernel_launch(void* const* d_in, const int* in_sizes, int n_in,
                              void* d_out, int out_size) {
    const float* x   = (const float*)d_in[0];
    const float* lin = (const float*)d_in[1];
    if (n_in >= 2 && in_sizes[0] < in_sizes[1]) {
        const float* tmp = x; x = lin; lin = tmp;
    }
    float* out = (float*)d_out;

    k0_init<<<1, 1>>>();
    k1_gemm<<<dim3(128, 4), 256>>>(x, lin);
    kver<<<256, 256>>>();
    k2p_prefix<<<dim3(2, 64), 256>>>();
    kscan<<<1024, 256>>>();
    kbad<<<8192, 256>>>();
    k4_zero_sum<<<1, 1>>>();
    k4_sum<<<128, 256>>>();
    kfill<<<1024, 256>>>(out);
}

// round 13
// speedup vs baseline: 5.8391x; 1.0292x over previous
#include <cuda_runtime.h>
#include <cstdint>

#define NN 8192
#define CC 256
#define TOPK 17
#define KNN 16
#define PRE 256

__device__ float g_h[NN * CC];
__device__ unsigned g_mask[NN * (PRE / 32)];        // 256 KB plateau bitmask
__device__ unsigned long long g_topk[NN * TOPK];
__device__ float g_sum;
__device__ int g_badlist[NN];
__device__ int g_badcnt;
__device__ int g_anomaly;
__device__ unsigned g_Vp_bits;

// Eigen/MLIR fast-tanh FMA variant — bit-exact vs reference (proven R7/R9/R12).
__device__ __forceinline__ float ftanh(float x) {
    const float kMax = 7.99881172180175781f;
    float xc = fminf(fmaxf(x, -kMax), kMax);
    float x2 = __fmul_rn(xc, xc);
    float p = __fmaf_rn(x2, -2.76076847742355e-16f, 2.00018790482477e-13f);
    p = __fmaf_rn(x2, p, -8.60467152213735e-11f);
    p = __fmaf_rn(x2, p,  5.12229709037114e-08f);
    p = __fmaf_rn(x2, p,  1.48572235717979e-05f);
    p = __fmaf_rn(x2, p,  6.37261928875436e-04f);
    p = __fmaf_rn(x2, p,  4.89352455891786e-03f);
    p = __fmul_rn(xc, p);
    float q = __fmaf_rn(x2, 1.19825839466702e-06f, 1.18534705686654e-04f);
    q = __fmaf_rn(x2, q, 2.26843463243900e-03f);
    q = __fmaf_rn(x2, q, 4.89352518554385e-03f);
    float r = __fdiv_rn(p, q);
    return (fabsf(x) < 0.0004f) ? x : r;
}
__device__ __forceinline__ float act(float x) { return fmaxf(ftanh(x), 0.0f); }

__global__ void k0_init() {
    g_anomaly = 0; g_badcnt = 0; g_Vp_bits = __float_as_uint(act(8.0f));
}

// Verify: no fp32 x in [2.0, kMax) has act(x) > V_p. Below 2.0, tanh<=0.9641.
__global__ void __launch_bounds__(256) kver() {
    unsigned lo = __float_as_uint(2.0f);
    unsigned hi = __float_as_uint(7.99881172180175781f);
    float Vp = act(8.0f);
    unsigned i = lo + blockIdx.x * blockDim.x + threadIdx.x;
    unsigned stride = gridDim.x * blockDim.x;
    bool bad = false;
    for (; i < hi; i += stride) bad |= (act(__uint_as_float(i)) > Vp);
    if (__syncthreads_or(bad) && threadIdx.x == 0) g_anomaly = 1;
}

// K1: h = x @ lin (unchanged — proven bits)
__global__ void __launch_bounds__(256) k1_gemm(const float* __restrict__ x,
                                               const float* __restrict__ lin) {
    __shared__ float As[16][64], Bs[16][64];
    int bm = blockIdx.x, bn = blockIdx.y, tid = threadIdx.x;
    int tx = tid & 15, ty = tid >> 4;
    int ar = tid >> 2, ak = (tid & 3) * 4;
    int bk = tid >> 4, bc = (tid & 15) * 4;
    float acc[4][4];
#pragma unroll
    for (int i = 0; i < 4; i++)
#pragma unroll
        for (int j = 0; j < 4; j++) acc[i][j] = 0.f;
    for (int kt = 0; kt < CC; kt += 16) {
        float4 av = *(const float4*)(x + (size_t)(bm * 64 + ar) * CC + kt + ak);
        float4 bv = *(const float4*)(lin + (size_t)(kt + bk) * CC + bn * 64 + bc);
        __syncthreads();
        As[ak + 0][ar] = av.x; As[ak + 1][ar] = av.y;
        As[ak + 2][ar] = av.z; As[ak + 3][ar] = av.w;
        *(float4*)&Bs[bk][bc] = bv;
        __syncthreads();
#pragma unroll
        for (int kk = 0; kk < 16; kk++) {
            float a[4], b[4];
#pragma unroll
            for (int i = 0; i < 4; i++) a[i] = As[kk][ty * 4 + i];
#pragma unroll
            for (int j = 0; j < 4; j++) b[j] = Bs[kk][tx * 4 + j];
#pragma unroll
            for (int i = 0; i < 4; i++)
#pragma unroll
                for (int j = 0; j < 4; j++) acc[i][j] = __fmaf_rn(a[i], b[j], acc[i][j]);
        }
    }
#pragma unroll
    for (int i = 0; i < 4; i++)
        *(float4*)(g_h + (size_t)(bm * 64 + ty * 4 + i) * CC + bn * 64 + tx * 4) =
            make_float4(acc[i][0], acc[i][1], acc[i][2], acc[i][3]);
}

// K2p: exact fp32 prefix panel, epilogue writes plateau BITMASK only.
// Dot FMA chains: strictly sequential k 0..255 — bits identical to R12 (passed 0.0).
__global__ void __launch_bounds__(256) k2p_prefix() {
    __shared__ float As[16][128], Bs[16][128];
    int bj = blockIdx.x, bi = blockIdx.y;     // bj in [0,2), bi in [0,64)
    int tid = threadIdx.x;
    int tx = tid & 15, ty = tid >> 4;
    int lr = tid >> 1, lk = (tid & 1) * 8;
    const float* ap = g_h + (size_t)(bi * 128 + lr) * CC + lk;
    const float* bp = g_h + (size_t)(bj * 128 + lr) * CC + lk;

    float acc[8][8];
#pragma unroll
    for (int i = 0; i < 8; i++)
#pragma unroll
        for (int j = 0; j < 8; j++) acc[i][j] = 0.f;

    for (int kt = 0; kt < CC; kt += 16) {
        float4 a0 = *(const float4*)(ap + kt);
        float4 a1 = *(const float4*)(ap + kt + 4);
        float4 b0 = *(const float4*)(bp + kt);
        float4 b1 = *(const float4*)(bp + kt + 4);
        __syncthreads();
        As[lk + 0][lr] = a0.x; As[lk + 1][lr] = a0.y;
        As[lk + 2][lr] = a0.z; As[lk + 3][lr] = a0.w;
        As[lk + 4][lr] = a1.x; As[lk + 5][lr] = a1.y;
        As[lk + 6][lr] = a1.z; As[lk + 7][lr] = a1.w;
        Bs[lk + 0][lr] = b0.x; Bs[lk + 1][lr] = b0.y;
        Bs[lk + 2][lr] = b0.z; Bs[lk + 3][lr] = b0.w;
        Bs[lk + 4][lr] = b1.x; Bs[lk + 5][lr] = b1.y;
        Bs[lk + 6][lr] = b1.z; Bs[lk + 7][lr] = b1.w;
        __syncthreads();
#pragma unroll
        for (int kk = 0; kk < 16; kk++) {
            float a[8], b[8];
#pragma unroll
            for (int i = 0; i < 8; i++) a[i] = As[kk][ty * 8 + i];
#pragma unroll
            for (int j = 0; j < 8; j++) b[j] = Bs[kk][tx * 8 + j];
#pragma unroll
            for (int i = 0; i < 8; i++)
#pragma unroll
                for (int j = 0; j < 8; j++) acc[i][j] = __fmaf_rn(a[i], b[j], acc[i][j]);
        }
    }
    // Epilogue: plateau mask. col = bj*128 + tx*8 + j; bit in word = (tx&3)*8 + j.
    unsigned vp = g_Vp_bits;
    int r0 = bi * 128 + ty * 8;
    int wcol = bj * 4 + (tx >> 2);            // word index within row (of 8)
    unsigned lane = tid & 31;
#pragma unroll
    for (int i = 0; i < 8; i++) {
        unsigned byte = 0;
#pragma unroll
        for (int j = 0; j < 8; j++)
            byte |= (__float_as_uint(act(acc[i][j])) == vp ? 1u : 0u) << j;
        unsigned w = byte << ((lane & 3) * 8);
        w |= __shfl_xor_sync(0xffffffffu, w, 1);
        w |= __shfl_xor_sync(0xffffffffu, w, 2);
        if ((lane & 3) == 0) g_mask[(size_t)(r0 + i) * 8 + wcol] = w;
    }
}

// kscan: first 17 plateau cols per row from the bitmask; short rows -> badlist.
// On tanh anomaly, every row goes to the badlist (exact full recompute).
__global__ void __launch_bounds__(256) kscan() {
    int row = blockIdx.x * 8 + (threadIdx.x >> 5);
    int lane = threadIdx.x & 31;
    unsigned vp = g_Vp_bits;
    int an = g_anomaly;
    unsigned w = (lane < 8) ? g_mask[(size_t)row * 8 + lane] : 0u;
    int cnt = 0;
    if (!an) {
#pragma unroll
        for (int wi = 0; wi < 8; wi++) {
            unsigned ww = __shfl_sync(0xffffffffu, w, wi);
            if (lane == 0) {
                while (ww && cnt < TOPK) {
                    int l = __ffs(ww) - 1; ww &= ww - 1;
                    unsigned col = wi * 32 + l;
                    g_topk[row * TOPK + cnt] =
                        ((unsigned long long)vp << 32) | (0xFFFFFFFFu - col);
                    cnt++;
                }
            }
            cnt = __shfl_sync(0xffffffffu, cnt, 0);
            if (cnt >= TOPK) break;
        }
    }
    if (lane == 0 && (an || cnt < TOPK)) {
        int idx = atomicAdd(&g_badcnt, 1);
        g_badlist[idx] = row;
    }
}

__device__ __forceinline__ void tk_insert(unsigned long long (&loc)[TOPK],
                                          unsigned long long key) {
    if (key > loc[TOPK - 1]) {
        loc[TOPK - 1] = key;
#pragma unroll
        for (int q = TOPK - 1; q > 0; q--) {
            unsigned long long a = loc[q - 1], b = loc[q];
            if (b > a) { loc[q - 1] = b; loc[q] = a; }
        }
    }
}
__device__ __forceinline__ unsigned long long warpmax_u64(unsigned long long v) {
#pragma unroll
    for (int off = 16; off; off >>= 1) {
        unsigned long long o = __shfl_xor_sync(0xffffffffu, v, off);
        if (o > v) v = o;
    }
    return v;
}
__device__ void topk_merge_write(unsigned long long (&loc)[TOPK], int row) {
    __shared__ unsigned long long wl[8][TOPK];
    int lane = threadIdx.x & 31, wp = threadIdx.x >> 5;
    for (int it = 0; it < TOPK; it++) {
        unsigned long long best = warpmax_u64(loc[0]);
        unsigned m = __ballot_sync(0xffffffffu, loc[0] == best);
        if (lane == (__ffs(m) - 1)) {
#pragma unroll
            for (int q = 0; q < TOPK - 1; q++) loc[q] = loc[q + 1];
            loc[TOPK - 1] = 0ull;
        }
        if (lane == 0) wl[wp][it] = best;
    }
    __syncthreads();
    if (wp == 0) {
        int p = 0;
        for (int it = 0; it < TOPK; it++) {
            unsigned long long cand = (lane < 8) ? wl[lane][p] : 0ull;
            unsigned long long best = warpmax_u64(cand);
            unsigned m = __ballot_sync(0xffffffffu, (cand == best) && (lane < 8));
            if (lane == (__ffs(m) - 1)) p++;
            if (lane == 0) g_topk[row * TOPK + it] = best;
        }
    }
}

// kbad: exact full-row top-k for each listed bad row (normally zero rows).
// Same sequential-k fma order -> identical dot bits. Grid-stride over list.
__global__ void __launch_bounds__(256) kbad() {
    __shared__ float hr[CC];
    int nb = g_badcnt;
    int tid = threadIdx.x;
    for (int b = blockIdx.x; b < nb; b += gridDim.x) {
        int row = g_badlist[b];
        __syncthreads();
        hr[tid] = g_h[(size_t)row * CC + tid];
        __syncthreads();
        unsigned long long loc[TOPK];
#pragma unroll
        for (int q = 0; q < TOPK; q++) loc[q] = 0ull;
        for (int j = tid; j < NN; j += 256) {
            const float4* bp = (const float4*)(g_h + (size_t)j * CC);
            float accv = 0.f;
            for (int k4i = 0; k4i < CC / 4; k4i++) {
                float4 bb = bp[k4i];
                accv = __fmaf_rn(hr[k4i * 4 + 0], bb.x, accv);
                accv = __fmaf_rn(hr[k4i * 4 + 1], bb.y, accv);
                accv = __fmaf_rn(hr[k4i * 4 + 2], bb.z, accv);
                accv = __fmaf_rn(hr[k4i * 4 + 3], bb.w, accv);
            }
            float v = act(accv);
            tk_insert(loc, ((unsigned long long)__float_as_uint(v) << 32) |
                           (0xFFFFFFFFu - (unsigned)j));
        }
        topk_merge_write(loc, row);
        __syncthreads();
    }
}

__global__ void k4_zero_sum() { g_sum = 0.f; }
__global__ void __launch_bounds__(256) k4_sum() {
    int i = blockIdx.x * blockDim.x + threadIdx.x;
    int stride = gridDim.x * blockDim.x;
    float s = 0.f;
    for (int e = i; e < NN * TOPK; e += stride) {
        unsigned long long key = g_topk[e];
        int row = e / TOPK;
        unsigned col = 0xFFFFFFFFu - (unsigned)(key & 0xFFFFFFFFull);
        float v = __uint_as_float((unsigned)(key >> 32));
        if (col < NN && col != (unsigned)row) s += v;
    }
    __shared__ float sh[256];
    sh[threadIdx.x] = s;
    __syncthreads();
    for (int st = 128; st; st >>= 1) {
        if (threadIdx.x < st) sh[threadIdx.x] += sh[threadIdx.x + st];
        __syncthreads();
    }
    if (threadIdx.x == 0) atomicAdd(&g_sum, sh[0]);
}

// k5_zero: 256 MB zero-fill — runs on a side stream, overlapped with compute.
__global__ void __launch_bounds__(256) k5_zero(float4* __restrict__ out) {
    size_t i = (size_t)blockIdx.x * blockDim.x + threadIdx.x;
    size_t stride = (size_t)gridDim.x * blockDim.x;
    float4 z = make_float4(0.f, 0.f, 0.f, 0.f);
    for (; i < (size_t)NN * NN / 4; i += stride) out[i] = z;
}

// k6_scatter: after zero join + k4_sum.
__global__ void __launch_bounds__(256) k6_scatter(float* __restrict__ out) {
    int row = blockIdx.x * 8 + (threadIdx.x >> 5);
    int lane = threadIdx.x & 31;
    float mean = g_sum / (float)(KNN * NN);
    if (lane < TOPK) {
        unsigned long long key = g_topk[row * TOPK + lane];
        unsigned col = 0xFFFFFFFFu - (unsigned)(key & 0xFFFFFFFFull);
        float v = __uint_as_float((unsigned)(key >> 32));
        if (col < NN && col != (unsigned)row)
            out[(size_t)row * NN + col] = __fdiv_rn(v, mean);
    }
}

extern "C" void kernel_launch(void* const* d_in, const int* in_sizes, int n_in,
                              void* d_out, int out_size) {
    const float* x   = (const float*)d_in[0];
    const float* lin = (const float*)d_in[1];
    if (n_in >= 2 && in_sizes[0] < in_sizes[1]) {
        const float* tmp = x; x = lin; lin = tmp;
    }
    float* out = (float*)d_out;

    static cudaStream_t s2 = nullptr;
    static cudaEvent_t e0 = nullptr, e1 = nullptr;
    if (!s2) {
        cudaStreamCreateWithFlags(&s2, cudaStreamNonBlocking);
        cudaEventCreateWithFlags(&e0, cudaEventDisableTiming);
        cudaEventCreateWithFlags(&e1, cudaEventDisableTiming);
    }

    // Fork: zero-fill (HBM-bound) overlaps the FMA-bound compute chain.
    cudaEventRecord(e0, 0);
    cudaStreamWaitEvent(s2, e0, 0);
    k5_zero<<<2048, 256, 0, s2>>>((float4*)out);
    cudaEventRecord(e1, s2);

    k0_init<<<1, 1>>>();
    k1_gemm<<<dim3(128, 4), 256>>>(x, lin);
    kver<<<256, 256>>>();
    k2p_prefix<<<dim3(2, 64), 256>>>();
    kscan<<<1024, 256>>>();
    kbad<<<64, 256>>>();
    k4_zero_sum<<<1, 1>>>();
    k4_sum<<<128, 256>>>();

    // Join: zero-fill must complete before scatter.
    cudaStreamWaitEvent(0, e1, 0);
    k6_scatter<<<1024, 256>>>(out);
}